// round 16
// baseline (speedup 1.0000x reference)
#include <cuda_runtime.h>
#include <math.h>

#define BATCH 8
#define NPTS  8192
#define NSLOT 16                     // 8 batches x 2 clouds
#define TOTPTS (NSLOT * NPTS)        // 131072
#define G 32
#define NC (G * G * G)               // 32768 cells per grid
#define NCT (NSLOT * NC)             // 524288 cells total
#define NTILE 512                    // scan tiles (1024 cells each)
#define NWCHUNK 4096                 // query warps (32 queries each)
#define LOB  (-5.5f)
#define HCELL (11.0f / G)
#define INVH  (G / 11.0f)
#define EPSF 1e-10f

#define FLG_AGG 0x40000000u
#define FLG_INC 0x80000000u
#define VALMASK 0x3FFFFFFFu

// ---- static scratch (no allocation; zero-initialized at module load) ------
__device__ float4   g_pk[TOTPTS];      // packed points {x,y,z,|p|^2}
__device__ float4   g_sorted[TOTPTS];  // points sorted by cell (global CSR)
__device__ int      g_cell[TOTPTS];    // flat cell id per point
__device__ int      g_cnt[NCT];        // histogram (self-cleaned by scan)
__device__ int      g_start[NCT + 1];  // CSR starts + sentinel
__device__ int      g_cursor[NCT];     // scatter cursors
__device__ int      g_ticket;          // scan tile ticket (reset by final)
__device__ unsigned g_tstate[NTILE];   // lookback states  (reset by final)
__device__ float    g_wpart[NWCHUNK];  // per-query-warp partial sums

// ---------------------------------------------------------------------------
// Pack points (with |p|^2 in .w), compute cells, histogram.
// t in [0,131072): slot = t>>13 (b*2 + side), i = t&8191. side0=x, side1=y.
// ---------------------------------------------------------------------------
__global__ void assign_kernel(const float* __restrict__ x,
                              const float* __restrict__ y) {
    int t = blockIdx.x * 256 + threadIdx.x;
    int slot = t >> 13, i = t & (NPTS - 1);
    int b = slot >> 1;
    const float* src = (slot & 1) ? y : x;
    const float* p = src + ((size_t)b * NPTS + i) * 3;
    float px = p[0], py = p[1], pz = p[2];
    int cx = min(G - 1, max(0, (int)((px - LOB) * INVH)));
    int cy = min(G - 1, max(0, (int)((py - LOB) * INVH)));
    int cz = min(G - 1, max(0, (int)((pz - LOB) * INVH)));
    int c = slot * NC + ((cz * G + cy) * G + cx);
    float w = fmaf(px, px, fmaf(py, py, pz * pz));
    g_pk[t] = make_float4(px, py, pz, w);
    g_cell[t] = c;
    atomicAdd(&g_cnt[c], 1);
}

// ---------------------------------------------------------------------------
// Single-pass exclusive scan of g_cnt (decoupled lookback, ticket-ordered).
// Zeroes g_cnt for the next graph replay; fills g_start and g_cursor.
// ---------------------------------------------------------------------------
__global__ void __launch_bounds__(1024) scan_kernel() {
    __shared__ int tile_s, exc_s;
    __shared__ int ws[32];
    int tid = threadIdx.x, lane = tid & 31, w = tid >> 5;

    if (tid == 0) tile_s = atomicAdd(&g_ticket, 1);
    __syncthreads();
    const int tile = tile_s;
    const int i = tile * 1024 + tid;

    int v = g_cnt[i];
    g_cnt[i] = 0;                                  // self-clean for next call

    int s = v;
    #pragma unroll
    for (int o = 1; o < 32; o <<= 1) {
        int t = __shfl_up_sync(0xffffffffu, s, o);
        if (lane >= o) s += t;
    }
    if (lane == 31) ws[w] = s;
    __syncthreads();
    if (w == 0) {
        int t = ws[lane];
        #pragma unroll
        for (int o = 1; o < 32; o <<= 1) {
            int u = __shfl_up_sync(0xffffffffu, t, o);
            if (lane >= o) t += u;
        }
        ws[lane] = t;
    }
    __syncthreads();
    int local_exc = ((w > 0) ? ws[w - 1] : 0) + s - v;
    int total = ws[31];

    if (tid == 0) {
        if (tile == 0) {
            __threadfence();
            atomicExch(&g_tstate[0], FLG_INC | (unsigned)total);
            exc_s = 0;
        } else {
            __threadfence();
            atomicExch(&g_tstate[tile], FLG_AGG | (unsigned)total);
            int exc = 0, j = tile - 1;
            while (true) {
                unsigned st = atomicAdd(&g_tstate[j], 0u);
                if (st & FLG_INC) { exc += (int)(st & VALMASK); break; }
                if (st & FLG_AGG) { exc += (int)(st & VALMASK); j--; }
            }
            __threadfence();
            atomicExch(&g_tstate[tile], FLG_INC | (unsigned)(exc + total));
            exc_s = exc;
        }
    }
    __syncthreads();
    int e = exc_s + local_exc;
    g_start[i]  = e;
    g_cursor[i] = e;
    if (i == 0) g_start[NCT] = TOTPTS;
}

__global__ void scatter_kernel() {
    int t = blockIdx.x * 256 + threadIdx.x;
    int pos = atomicAdd(&g_cursor[g_cell[t]], 1);
    g_sorted[pos] = g_pk[t];
}

// ---------------------------------------------------------------------------
// Warp-uniform candidate scan: [s,e) is warp-uniform, so each g_sorted[j]
// load is a single broadcast wavefront; every lane evaluates the candidate
// against its own query via best = min(best, |p|^2 - 2<p,q>).
// ---------------------------------------------------------------------------
__device__ __forceinline__ void scanu(int s, int e,
                                      float nx, float ny, float nz,
                                      float& best) {
    for (int j = s; j < e; j++) {
        float4 p = g_sorted[j];
        best = fminf(best, fmaf(nx, p.x, fmaf(ny, p.y, fmaf(nz, p.z, p.w))));
    }
}

// ---------------------------------------------------------------------------
// Exact NN, WARP-UNIFORM: warp = 32 consecutive cell-sorted queries (same
// slot; 8192%32==0). Warp computes the bbox of its 32 query cells (shfl
// butterfly) and scans region(r) = bbox (+) r with uniform loops: uniform row
// ranges, uniform [s,e), broadcast candidate loads, zero divergence. Per-lane
// stop bound stays valid because each query's cell is inside the bbox: after
// region(r) is scanned, any unscanned point is >= r*HCELL from every query
// in the bbox (per-axis clamped assignment is 1-Lipschitz). Warp continues
// while ANY lane unsatisfied; worst case r=G => full scan => exact.
// ---------------------------------------------------------------------------
__global__ void __launch_bounds__(128) query_kernel() {
    const int gw   = blockIdx.x * 4 + (threadIdx.x >> 5);  // [0, 4096)
    const int lane = threadIdx.x & 31;
    const int qid  = gw * 32 + lane;
    const int d = qid >> 16;
    const int q = qid & 65535;
    const int b = q >> 13;
    const int i = q & (NPTS - 1);
    const int dbslot = b * 2 + (1 - d);

    float4 qp = g_sorted[(b * 2 + d) * NPTS + i];  // cell-sorted query
    const float qq = qp.w;                         // |q|^2
    const float nx = -2.0f * qp.x, ny = -2.0f * qp.y, nz = -2.0f * qp.z;

    int cx = min(G - 1, max(0, (int)((qp.x - LOB) * INVH)));
    int cy = min(G - 1, max(0, (int)((qp.y - LOB) * INVH)));
    int cz = min(G - 1, max(0, (int)((qp.z - LOB) * INVH)));

    // Warp bbox of query cells (butterfly min/max)
    int bx0 = cx, bx1 = cx, by0 = cy, by1 = cy, bz0 = cz, bz1 = cz;
    #pragma unroll
    for (int o = 16; o > 0; o >>= 1) {
        bx0 = min(bx0, __shfl_xor_sync(0xffffffffu, bx0, o));
        bx1 = max(bx1, __shfl_xor_sync(0xffffffffu, bx1, o));
        by0 = min(by0, __shfl_xor_sync(0xffffffffu, by0, o));
        by1 = max(by1, __shfl_xor_sync(0xffffffffu, by1, o));
        bz0 = min(bz0, __shfl_xor_sync(0xffffffffu, bz0, o));
        bz1 = max(bz1, __shfl_xor_sync(0xffffffffu, bz1, o));
    }

    const int base = dbslot * NC;
    float best = 1e30f;                            // min of (|p|^2 - 2<p,q>)

    // region(1): full rectangle bbox (+) 1
    {
        int z0 = max(bz0 - 1, 0), z1 = min(bz1 + 1, G - 1);
        int y0 = max(by0 - 1, 0), y1 = min(by1 + 1, G - 1);
        int x0 = max(bx0 - 1, 0), x1 = min(bx1 + 1, G - 1);
        for (int z = z0; z <= z1; z++)
            for (int y = y0; y <= y1; y++) {
                int row = base + (z * G + y) * G;
                scanu(g_start[row + x0], g_start[row + x1 + 1],
                      nx, ny, nz, best);
            }
    }

    // expanding shells around the bbox (warp-uniform)
    int r = 1;
    while (r < G) {
        float rh = (float)r * HCELL;
        bool done = (best + qq) <= rh * rh * 0.9999f;
        if (__all_sync(0xffffffffu, done)) break;
        r++;
        int z0 = max(bz0 - r, 0), z1 = min(bz1 + r, G - 1);
        int y0 = max(by0 - r, 0), y1 = min(by1 + r, G - 1);
        int x0 = max(bx0 - r, 0), x1 = min(bx1 + r, G - 1);
        for (int z = z0; z <= z1; z++) {
            bool zedge = (z == bz0 - r) || (z == bz1 + r);
            for (int y = y0; y <= y1; y++) {
                bool yedge = (y == by0 - r) || (y == by1 + r);
                int row = base + (z * G + y) * G;
                if (zedge | yedge) {
                    scanu(g_start[row + x0], g_start[row + x1 + 1],
                          nx, ny, nz, best);
                } else {
                    int xa = bx0 - r;
                    if (xa >= 0)
                        scanu(g_start[row + xa], g_start[row + xa + 1],
                              nx, ny, nz, best);
                    int xb = bx1 + r;
                    if (xb < G)
                        scanu(g_start[row + xb], g_start[row + xb + 1],
                              nx, ny, nz, best);
                }
            }
        }
    }

    // dist and deterministic per-warp sum (fixed lane tree)
    float d2 = fmaxf(best + qq, 0.0f);
    float dist = sqrtf(d2 + EPSF);
    #pragma unroll
    for (int o = 16; o > 0; o >>= 1)
        dist += __shfl_down_sync(0xffffffffu, dist, o);
    if (lane == 0) g_wpart[gw] = dist;
}

// ---------------------------------------------------------------------------
// Fold 4096 warp-partials -> 16 (d,b) sums -> max over d -> mean -> total.
// Warp-chunk c covers qids [c*32, c*32+32) => group = c >> 8 (256/group).
// Also resets scan ticket/states for the next graph replay.
// ---------------------------------------------------------------------------
__global__ void __launch_bounds__(512) final_kernel(float* __restrict__ out) {
    int t = threadIdx.x, grp = t >> 5, lane = t & 31;
    g_tstate[t] = 0u;
    if (t == 0) g_ticket = 0;

    float s = 0.0f;
    #pragma unroll
    for (int k = 0; k < 8; k++)
        s += g_wpart[grp * 256 + k * 32 + lane];
    #pragma unroll
    for (int o = 16; o > 0; o >>= 1)
        s += __shfl_down_sync(0xffffffffu, s, o);

    __shared__ float ss[16];
    if (lane == 0) ss[grp] = s;
    __syncthreads();
    if (t == 0) {
        float tot = 0.0f;
        #pragma unroll
        for (int bb = 0; bb < BATCH; bb++)
            tot += fmaxf(ss[bb], ss[8 + bb]) * (1.0f / NPTS);
        out[0] = tot;
    }
}

// ---------------------------------------------------------------------------
extern "C" void kernel_launch(void* const* d_in, const int* in_sizes, int n_in,
                              void* d_out, int out_size) {
    const float* x = (const float*)d_in[0];
    const float* y = (const float*)d_in[1];
    float* out = (float*)d_out;

    assign_kernel<<<TOTPTS / 256, 256>>>(x, y);
    scan_kernel<<<NTILE, 1024>>>();
    scatter_kernel<<<TOTPTS / 256, 256>>>();
    query_kernel<<<NWCHUNK / 4, 128>>>();
    final_kernel<<<1, 512>>>(out);
}